// round 16
// baseline (speedup 1.0000x reference)
#include <cuda_runtime.h>
#include <cstdint>

// Holonomy: out[b,l] = M_15 @ ... @ M_1 @ M_0,  M_t = Gamma[b, loops[l][t+1], loops[l][t]]
// Gamma: [4, 512, 512, 8, 8] fp32; loops: [64, 17] int (32 or 64 bit); out: [4,64,8,8] fp32.
//
// One WARP per chain; fully warp-synchronous, no smem, no barriers.
// float2 layout: lane L holds flat elements 2L and 2L+1 of each 8x8 matrix,
// i.e. M[row][col], M[row][col+1] with row = L>>2, col = (L&3)*2.
// Layout is closed under the shuffle-matmul; every gather is one LDG.64.
// The 15 products form a balanced TREE (depth 4). mm8 uses split (even/odd k)
// accumulator chains to halve the serial FMA depth on the tree's serial levels.
//
// loops dtype detected per-warp: int64 data (values < 2^31) has every odd
// 32-bit word zero; 32 sampled odd words all-zero under int32 random data
// in [0,512) has probability 512^-32.

#define BATCH   4
#define SEQ     512
#define NLOOPS  64
#define LOOPLEN 17
#define NSTEPS  (LOOPLEN - 1)    // 16
#define NCHAINS (BATCH * NLOOPS) // 256
#define WARPS_PER_BLOCK 4
#define FULLMASK 0xffffffffu

// P = A @ B in the float2 lane layout. row = lane>>2, cq = lane&3.
// Split accumulators: even-k and odd-k chains run independently (depth 16
// instead of 32), merged with one FADD per output.
__device__ __forceinline__ float2 mm8(float2 a, float2 bm, int row, int cq)
{
    float e0 = 0.f, e1 = 0.f, o0 = 0.f, o1 = 0.f;
    #pragma unroll
    for (int kk = 0; kk < 4; kk++) {
        const int k0 = 2 * kk;       // even k: A element .x
        const int k1 = 2 * kk + 1;   // odd  k: A element .y
        // A[row][k] -> lane row*4 + (k>>1); B[k][col+d] -> lane k*4 + cq
        const float ae  = __shfl_sync(FULLMASK, a.x,  row * 4 + kk);
        const float ao  = __shfl_sync(FULLMASK, a.y,  row * 4 + kk);
        const float be0 = __shfl_sync(FULLMASK, bm.x, k0 * 4 + cq);
        const float be1 = __shfl_sync(FULLMASK, bm.y, k0 * 4 + cq);
        const float bo0 = __shfl_sync(FULLMASK, bm.x, k1 * 4 + cq);
        const float bo1 = __shfl_sync(FULLMASK, bm.y, k1 * 4 + cq);
        e0 = fmaf(ae, be0, e0);
        e1 = fmaf(ae, be1, e1);
        o0 = fmaf(ao, bo0, o0);
        o1 = fmaf(ao, bo1, o1);
    }
    return make_float2(e0 + o0, e1 + o1);
}

__global__ void __launch_bounds__(32 * WARPS_PER_BLOCK, 8) holonomy_kernel(
    const float* __restrict__ Gamma,
    const int*   __restrict__ loops_w,   // raw 32-bit view of loops buffer
    float* __restrict__ out)
{
    const int lane = threadIdx.x & 31;
    const int w    = blockIdx.x * WARPS_PER_BLOCK + (threadIdx.x >> 5); // chain 0..255
    const int b    = w >> 6;
    const int row  = lane >> 2;        // 0..7
    const int cq   = lane & 3;         // column pair 0..3

    // ---- issue ALL front-end loads concurrently (one memory round trip) ----
    const int det = loops_w[2 * lane + 1];            // words 1..63: in-bounds for both dtypes
    const int l   = w & (NLOOPS - 1);
    const int e   = l * LOOPLEN + (lane < LOOPLEN ? lane : LOOPLEN - 1);
    const int c32 = loops_w[e];                       // int32 interpretation
    const int c64 = loops_w[2 * e];                   // int64 (low word) interpretation

    const unsigned nz = __ballot_sync(FULLMASK, det != 0);
    const int v = ((nz == 0u) ? c64 : c32) & (SEQ - 1);   // defensive mask: never OOB

    // lane t (t < 16) computes the element offset of matrix t once
    const int vn  = __shfl_down_sync(FULLMASK, v, 1);     // idx[t+1]
    const int ofs = (vn * SEQ + v) * 64;                  // < 2^25, fits int

    // ---- gather all 16 matrices: one coalesced LDG.64 per matrix ----
    const float2* Gb = (const float2*)(Gamma + (size_t)b * (SEQ * SEQ * 64));
    float2 Mt[NSTEPS];
    #pragma unroll
    for (int t = 0; t < NSTEPS; t++) {
        const int o = __shfl_sync(FULLMASK, ofs, t);
        Mt[t] = Gb[(o >> 1) + lane];
    }

    // ---- balanced tree product (in place, ascending composition) ----
    #pragma unroll
    for (int i = 0; i < 8; i++)   // level 1: 8 independent matmuls
        Mt[2*i] = mm8(Mt[2*i+1], Mt[2*i], row, cq);
    #pragma unroll
    for (int i = 0; i < 4; i++)   // level 2: 4 independent
        Mt[4*i] = mm8(Mt[4*i+2], Mt[4*i], row, cq);
    #pragma unroll
    for (int i = 0; i < 2; i++)   // level 3: 2 independent
        Mt[8*i] = mm8(Mt[8*i+4], Mt[8*i], row, cq);
    Mt[0] = mm8(Mt[8], Mt[0], row, cq);   // level 4 == M15 ... M0

    ((float2*)(out + (size_t)w * 64))[lane] = Mt[0];
}

extern "C" void kernel_launch(void* const* d_in, const int* in_sizes, int n_in,
                              void* d_out, int out_size)
{
    // Defensive input-order resolution via element counts:
    // Gamma = 67,108,864 elems; loops = 1088 elems.
    int gi = 0, li = 1;
    if (n_in >= 2 && in_sizes[0] < in_sizes[1]) { gi = 1; li = 0; }

    const float* Gamma   = (const float*)d_in[gi];
    const int*   loops_w = (const int*)d_in[li];
    float*       out     = (float*)d_out;

    holonomy_kernel<<<NCHAINS / WARPS_PER_BLOCK, 32 * WARPS_PER_BLOCK>>>(Gamma, loops_w, out);
}